// round 15
// baseline (speedup 1.0000x reference)
#include <cuda_runtime.h>

#define BB 64
#define TT 2048
#define DD 512

// Scratch (allocation-free contract: __device__ globals)
__device__ float g_phis[BB * DD];
__device__ float g_v[BB * DD];
__device__ float g_eh[BB * TT * 2];   // interleaved [e, hsum] per row
__device__ float g_blkmax[8192];      // per-block score max
__device__ float g_blksum[8192];      // per-block sum of exp(e - blkmax)
__device__ int   g_cnt[BB];           // arrival counters (zero-init; reset by last block)

// ---------------------------------------------------------------------------
// k_phis: phi_s[b,a] = dot(s[b,:], phi_w[a,:]) + phi_b[a]
// grid (32 a-tiles, 64 b) = 2048 blocks x 256 threads. Each warp does 2 a's.
// ---------------------------------------------------------------------------
__global__ void k_phis(const float* __restrict__ s,
                       const float* __restrict__ phi_w,
                       const float* __restrict__ phi_b) {
    const int b    = blockIdx.y;
    const int tid  = threadIdx.x;          // 256
    const int lane = tid & 31;
    const int warp = tid >> 5;             // 8 warps

    __shared__ float sh_s[DD];
    sh_s[tid]       = s[(size_t)b * DD + tid];
    sh_s[tid + 256] = s[(size_t)b * DD + tid + 256];
    __syncthreads();
    const float4* s4 = (const float4*)sh_s;

    const int a0 = blockIdx.x * 16 + warp * 2;
    const int a1 = a0 + 1;
    const float4* w0 = (const float4*)(phi_w + (size_t)a0 * DD);
    const float4* w1 = (const float4*)(phi_w + (size_t)a1 * DD);

    float acc0 = 0.f, acc1 = 0.f;
    #pragma unroll
    for (int j = 0; j < 4; j++) {
        float4 wa = w0[lane + 32 * j];
        float4 wb = w1[lane + 32 * j];
        float4 sv = s4[lane + 32 * j];
        acc0 += wa.x * sv.x + wa.y * sv.y + wa.z * sv.z + wa.w * sv.w;
        acc1 += wb.x * sv.x + wb.y * sv.y + wb.z * sv.z + wb.w * sv.w;
    }
    acc0 += __shfl_xor_sync(0xffffffffu, acc0, 16);
    acc1 += __shfl_xor_sync(0xffffffffu, acc1, 16);
    float x = (lane & 16) ? acc1 : acc0;
    #pragma unroll
    for (int off = 8; off; off >>= 1)
        x += __shfl_xor_sync(0xffffffffu, x, off);
    if ((lane & 15) == 0) {
        const int a = (lane == 0) ? a0 : a1;
        g_phis[b * DD + a] = x + phi_b[a];
    }
}

// ---------------------------------------------------------------------------
// k_v: v[b,k] = sum_a phi_s[b,a] * psi_w[a,k]
// grid (16 b-quads, 4 k-slices) = 64 blocks x 512 threads (16 warps).
// psi_b dropped: softmax is shift-invariant to the per-b constant it adds.
// ---------------------------------------------------------------------------
__global__ void k_v(const float* __restrict__ psi_w) {
    const int b0   = blockIdx.x * 4;
    const int ks   = blockIdx.y;           // k-slice: 32 float4 columns
    const int tid  = threadIdx.x;          // 512
    const int lane = tid & 31;
    const int warp = tid >> 5;             // 16 warps

    __shared__ float  ph[4][DD];
    __shared__ float4 part[4][16][32];

    #pragma unroll
    for (int j = 0; j < 4; j++)
        ph[j][tid] = g_phis[(size_t)(b0 + j) * DD + tid];
    __syncthreads();

    const float4* w4 = (const float4*)psi_w;     // [512][128] float4
    const int col = ks * 32 + lane;              // 0..127

    float4 acc[4];
    #pragma unroll
    for (int j = 0; j < 4; j++) acc[j] = make_float4(0.f, 0.f, 0.f, 0.f);

    const int abase = warp * 32;
    #pragma unroll 4
    for (int i = 0; i < 32; i++) {
        const int a = abase + i;
        const float4 w = w4[(size_t)a * 128 + col];
        #pragma unroll
        for (int j = 0; j < 4; j++) {
            const float p = ph[j][a];
            acc[j].x += p * w.x; acc[j].y += p * w.y;
            acc[j].z += p * w.z; acc[j].w += p * w.w;
        }
    }
    #pragma unroll
    for (int j = 0; j < 4; j++) part[j][warp][lane] = acc[j];
    __syncthreads();

    if (warp < 4) {
        float4 r = part[warp][0][lane];
        #pragma unroll
        for (int w = 1; w < 16; w++) {
            float4 p = part[warp][w][lane];
            r.x += p.x; r.y += p.y; r.z += p.z; r.w += p.w;
        }
        ((float4*)g_v)[(size_t)(b0 + warp) * 128 + col] = r;
    }
}

// ---------------------------------------------------------------------------
// k_scores: streaming pass + FUSED softmax finish (last block per b).
// Proven core: grid 8192 x 256, launch_bounds(256,4), v staged via smem,
// __ldcs h loads, folded 9-SHFL reduction.
// Epilogue: block computes (blkmax, blksumexp); fences; ONE atomicAdd per
// block on g_cnt[b]. The 128th arrival merges the 128 partials into (M, S),
// resets the counter, and scales all 2048 outputs for this b.
// ---------------------------------------------------------------------------
__global__ void __launch_bounds__(256, 4) k_scores(const float* __restrict__ h,
                                                   float* __restrict__ out) {
    const int tid  = threadIdx.x;
    const int lane = tid & 31;
    const int warp = tid >> 5;
    const int row0 = blockIdx.x * 16 + warp * 2;
    const int b    = blockIdx.x >> 7;      // 128 blocks per b

    __shared__ float sh_v[DD];
    __shared__ float sh_e[16];
    __shared__ int   sh_last;
    __shared__ float shM, shInv;

    ((float2*)sh_v)[tid] = ((const float2*)(g_v + (size_t)b * DD))[tid];
    __syncthreads();

    const float4* sv4 = (const float4*)sh_v;
    float4 v[4];
    #pragma unroll
    for (int j = 0; j < 4; j++) v[j] = sv4[lane + 32 * j];

    const float4* ha = (const float4*)(h + (size_t)row0 * DD);
    const float4* hb = ha + 128;
    float4 A[4], B[4];
    #pragma unroll
    for (int j = 0; j < 4; j++) A[j] = __ldcs(&ha[lane + 32 * j]);
    #pragma unroll
    for (int j = 0; j < 4; j++) B[j] = __ldcs(&hb[lane + 32 * j]);

    float e0 = 0.f, s0 = 0.f, e1 = 0.f, s1 = 0.f;
    #pragma unroll
    for (int j = 0; j < 4; j++) {
        e0 += A[j].x * v[j].x + A[j].y * v[j].y + A[j].z * v[j].z + A[j].w * v[j].w;
        s0 += (A[j].x + A[j].y) + (A[j].z + A[j].w);
        e1 += B[j].x * v[j].x + B[j].y * v[j].y + B[j].z * v[j].z + B[j].w * v[j].w;
        s1 += (B[j].x + B[j].y) + (B[j].z + B[j].w);
    }

    // Folded 4-value warp reduction: 9 SHFLs, depth 5.
    e0 += __shfl_xor_sync(0xffffffffu, e0, 16);
    s0 += __shfl_xor_sync(0xffffffffu, s0, 16);
    e1 += __shfl_xor_sync(0xffffffffu, e1, 16);
    s1 += __shfl_xor_sync(0xffffffffu, s1, 16);
    float x = (lane & 16) ? e1 : e0;
    float y = (lane & 16) ? s1 : s0;
    x += __shfl_xor_sync(0xffffffffu, x, 8);
    y += __shfl_xor_sync(0xffffffffu, y, 8);
    float z = (lane & 8) ? y : x;
    #pragma unroll
    for (int off = 4; off; off >>= 1)
        z += __shfl_xor_sync(0xffffffffu, z, off);
    // lane 0: e0 | lane 8: s0 | lane 16: e1 | lane 24: s1
    if ((lane & 7) == 0)
        g_eh[2 * (size_t)row0 + (lane >> 3)] = z;   // coalesced 4-lane sector
    if (lane == 0)  sh_e[warp * 2]     = z;
    if (lane == 16) sh_e[warp * 2 + 1] = z;
    __syncthreads();

    // Warp 0: block max + block sum-exp from the 16 row scores.
    if (warp == 0) {
        float ev = (lane < 16) ? sh_e[lane] : -3.4e38f;
        float m = ev;
        #pragma unroll
        for (int off = 8; off; off >>= 1)
            m = fmaxf(m, __shfl_xor_sync(0xffffffffu, m, off));
        m = fmaxf(m, __shfl_xor_sync(0xffffffffu, m, 16));
        float ex = (lane < 16) ? __expf(ev - m) : 0.f;
        #pragma unroll
        for (int off = 16; off; off >>= 1)
            ex += __shfl_xor_sync(0xffffffffu, ex, off);
        if (lane == 0) {
            g_blkmax[blockIdx.x] = m;
            g_blksum[blockIdx.x] = ex;
        }
    }
    // Make this block's g_eh/g_blkmax/g_blksum stores globally visible,
    // THEN arrive. (syncthreads orders all threads' fences before tid 0's atomic.)
    __threadfence();
    __syncthreads();
    if (tid == 0) {
        const int old = atomicAdd(&g_cnt[b], 1);
        sh_last = (old == 127);
    }
    __syncthreads();
    if (!sh_last) return;

    // ---- last block for this b: merge + scale (replaces k_softmax) ----
    if (tid == 0) g_cnt[b] = 0;            // reset for next graph replay
    __threadfence();                        // acquire side
    if (warp == 0) {
        const float4 bm = ((const float4*)(g_blkmax + b * 128))[lane];
        float m = fmaxf(fmaxf(bm.x, bm.y), fmaxf(bm.z, bm.w));
        #pragma unroll
        for (int off = 16; off; off >>= 1)
            m = fmaxf(m, __shfl_xor_sync(0xffffffffu, m, off));
        const float4 bs = ((const float4*)(g_blksum + b * 128))[lane];
        float sum = bs.x * __expf(bm.x - m) + bs.y * __expf(bm.y - m)
                  + bs.z * __expf(bm.z - m) + bs.w * __expf(bm.w - m);
        #pragma unroll
        for (int off = 16; off; off >>= 1)
            sum += __shfl_xor_sync(0xffffffffu, sum, off);
        if (lane == 0) { shM = m; shInv = 1.f / sum; }
    }
    __syncthreads();
    const float M = shM, inv = shInv;

    const float4* ehb = (const float4*)(g_eh + 2 * (size_t)b * TT);
    float2*       ob  = (float2*)(out + (size_t)b * TT);
    #pragma unroll
    for (int i = 0; i < 4; i++) {
        const int idx = tid + i * 256;      // 1024 float4s cover 2048 rows
        const float4 eh = ehb[idx];
        float2 o;
        o.x = __expf(eh.x - M) * inv * eh.y;
        o.y = __expf(eh.z - M) * inv * eh.w;
        ob[idx] = o;
    }
}

// ---------------------------------------------------------------------------
extern "C" void kernel_launch(void* const* d_in, const int* in_sizes, int n_in,
                              void* d_out, int out_size) {
    const float* s     = (const float*)d_in[0];   // [64, 512]
    const float* h     = (const float*)d_in[1];   // [64, 2048, 512]
    const float* phi_w = (const float*)d_in[2];   // [512, 512]
    const float* phi_b = (const float*)d_in[3];   // [512]
    const float* psi_w = (const float*)d_in[4];   // [512, 512]
    // d_in[5] = psi_b: unused (softmax shift invariance)
    float* out = (float*)d_out;                   // [64, 2048] fp32

    k_phis<<<dim3(32, 64), 256>>>(s, phi_w, phi_b);
    k_v<<<dim3(16, 4), 512>>>(psi_w);
    k_scores<<<8192, 256>>>(h, out);   // fused: scores + softmax finish
}

// round 16
// speedup vs baseline: 1.1531x; 1.1531x over previous
#include <cuda_runtime.h>

#define BB 64
#define TT 2048
#define DD 512

// Scratch (allocation-free contract: __device__ globals)
__device__ float g_phis[BB * DD];
__device__ float g_v[BB * DD];
__device__ float g_e[BB * TT];
__device__ float g_hsum[BB * TT];

// ---------------------------------------------------------------------------
// k_phis: phi_s[b,a] = dot(s[b,:], phi_w[a,:]) + phi_b[a]
// grid (32 a-tiles, 8 b-octets) = 256 blocks x 256 threads.
// Each warp pins 2 phi_w rows in registers ONCE and loops over 8 b's from
// smem -> 8x less phi_w read traffic than the per-b grid (round-9 version).
// ---------------------------------------------------------------------------
__global__ void k_phis(const float* __restrict__ s,
                       const float* __restrict__ phi_w,
                       const float* __restrict__ phi_b) {
    const int b0   = blockIdx.y * 8;
    const int tid  = threadIdx.x;          // 256
    const int lane = tid & 31;
    const int warp = tid >> 5;             // 8 warps

    __shared__ float sh_s[8][DD];          // 16 KB
    {
        const float4* src = (const float4*)(s + (size_t)b0 * DD);
        float4* dst = (float4*)&sh_s[0][0];
        #pragma unroll
        for (int i = 0; i < 4; i++)
            dst[tid + i * 256] = src[tid + i * 256];   // 1024 float4 total
    }
    __syncthreads();

    const int a0 = blockIdx.x * 16 + warp * 2;
    const int a1 = a0 + 1;
    const float4* w0 = (const float4*)(phi_w + (size_t)a0 * DD);
    const float4* w1 = (const float4*)(phi_w + (size_t)a1 * DD);
    float4 wa[4], wb[4];
    #pragma unroll
    for (int j = 0; j < 4; j++) { wa[j] = w0[lane + 32 * j]; wb[j] = w1[lane + 32 * j]; }
    const float bias0 = phi_b[a0];
    const float bias1 = phi_b[a1];

    #pragma unroll 1
    for (int bi = 0; bi < 8; bi++) {
        const float4* s4 = (const float4*)sh_s[bi];
        float acc0 = 0.f, acc1 = 0.f;
        #pragma unroll
        for (int j = 0; j < 4; j++) {
            const float4 sv = s4[lane + 32 * j];
            acc0 += wa[j].x * sv.x + wa[j].y * sv.y + wa[j].z * sv.z + wa[j].w * sv.w;
            acc1 += wb[j].x * sv.x + wb[j].y * sv.y + wb[j].z * sv.z + wb[j].w * sv.w;
        }
        // Folded 2-value warp reduction: 6 SHFLs, depth 5.
        acc0 += __shfl_xor_sync(0xffffffffu, acc0, 16);
        acc1 += __shfl_xor_sync(0xffffffffu, acc1, 16);
        float x = (lane & 16) ? acc1 : acc0;
        #pragma unroll
        for (int off = 8; off; off >>= 1)
            x += __shfl_xor_sync(0xffffffffu, x, off);
        if ((lane & 15) == 0) {
            const int a = (lane == 0) ? a0 : a1;
            const float bias = (lane == 0) ? bias0 : bias1;
            g_phis[(b0 + bi) * DD + a] = x + bias;
        }
    }
}

// ---------------------------------------------------------------------------
// k_v: v[b,k] = sum_a phi_s[b,a] * psi_w[a,k]
// grid (16 b-quads, 4 k-slices) = 64 blocks x 512 threads (16 warps).
// psi_b dropped: softmax is shift-invariant to the per-b constant it adds.
// ---------------------------------------------------------------------------
__global__ void k_v(const float* __restrict__ psi_w) {
    const int b0   = blockIdx.x * 4;
    const int ks   = blockIdx.y;           // k-slice: 32 float4 columns
    const int tid  = threadIdx.x;          // 512
    const int lane = tid & 31;
    const int warp = tid >> 5;             // 16 warps

    __shared__ float  ph[4][DD];
    __shared__ float4 part[4][16][32];

    #pragma unroll
    for (int j = 0; j < 4; j++)
        ph[j][tid] = g_phis[(size_t)(b0 + j) * DD + tid];
    __syncthreads();

    const float4* w4 = (const float4*)psi_w;     // [512][128] float4
    const int col = ks * 32 + lane;              // 0..127

    float4 acc[4];
    #pragma unroll
    for (int j = 0; j < 4; j++) acc[j] = make_float4(0.f, 0.f, 0.f, 0.f);

    const int abase = warp * 32;
    #pragma unroll 4
    for (int i = 0; i < 32; i++) {
        const int a = abase + i;
        const float4 w = w4[(size_t)a * 128 + col];
        #pragma unroll
        for (int j = 0; j < 4; j++) {
            const float p = ph[j][a];
            acc[j].x += p * w.x; acc[j].y += p * w.y;
            acc[j].z += p * w.z; acc[j].w += p * w.w;
        }
    }
    #pragma unroll
    for (int j = 0; j < 4; j++) part[j][warp][lane] = acc[j];
    __syncthreads();

    if (warp < 4) {
        float4 r = part[warp][0][lane];
        #pragma unroll
        for (int w = 1; w < 16; w++) {
            float4 p = part[warp][w][lane];
            r.x += p.x; r.y += p.y; r.z += p.z; r.w += p.w;
        }
        ((float4*)g_v)[(size_t)(b0 + warp) * 128 + col] = r;
    }
}

// ---------------------------------------------------------------------------
// k_scores: the DRAM-bound pass (one 268 MB streaming read of h).
// EXACT round-9 proven core (best measured, 55.4us total): grid 8192 x 256,
// launch_bounds(256,4), v staged via smem once per block, __ldcs h loads.
// ---------------------------------------------------------------------------
__global__ void __launch_bounds__(256, 4) k_scores(const float* __restrict__ h) {
    const int tid  = threadIdx.x;
    const int lane = tid & 31;
    const int warp = tid >> 5;
    const int row0 = blockIdx.x * 16 + warp * 2;
    const int b    = blockIdx.x >> 7;      // 128 blocks per b

    __shared__ float sh_v[DD];
    ((float2*)sh_v)[tid] = ((const float2*)(g_v + (size_t)b * DD))[tid];
    __syncthreads();

    const float4* sv4 = (const float4*)sh_v;
    float4 v[4];
    #pragma unroll
    for (int j = 0; j < 4; j++) v[j] = sv4[lane + 32 * j];

    const float4* ha = (const float4*)(h + (size_t)row0 * DD);
    const float4* hb = ha + 128;
    float4 A[4], B[4];
    #pragma unroll
    for (int j = 0; j < 4; j++) A[j] = __ldcs(&ha[lane + 32 * j]);
    #pragma unroll
    for (int j = 0; j < 4; j++) B[j] = __ldcs(&hb[lane + 32 * j]);

    float e0 = 0.f, s0 = 0.f, e1 = 0.f, s1 = 0.f;
    #pragma unroll
    for (int j = 0; j < 4; j++) {
        e0 += A[j].x * v[j].x + A[j].y * v[j].y + A[j].z * v[j].z + A[j].w * v[j].w;
        s0 += (A[j].x + A[j].y) + (A[j].z + A[j].w);
        e1 += B[j].x * v[j].x + B[j].y * v[j].y + B[j].z * v[j].z + B[j].w * v[j].w;
        s1 += (B[j].x + B[j].y) + (B[j].z + B[j].w);
    }
    #pragma unroll
    for (int off = 16; off; off >>= 1) {
        e0 += __shfl_xor_sync(0xffffffffu, e0, off);
        s0 += __shfl_xor_sync(0xffffffffu, s0, off);
        e1 += __shfl_xor_sync(0xffffffffu, e1, off);
        s1 += __shfl_xor_sync(0xffffffffu, s1, off);
    }
    if (lane == 0) {
        *(float2*)(g_e    + row0) = make_float2(e0, e1);
        *(float2*)(g_hsum + row0) = make_float2(s0, s1);
    }
}

// ---------------------------------------------------------------------------
// k_softmax: per-b softmax over T=2048 + output c = alpha * hsum.
// EXACT round-9 version: 64 blocks x 1024 threads (2 e/thread).
// ---------------------------------------------------------------------------
__global__ void k_softmax(float* __restrict__ out) {
    const int b    = blockIdx.x;
    const int tid  = threadIdx.x;          // 1024 -> 2 elems/thread
    const int lane = tid & 31;
    const int warp = tid >> 5;             // 32 warps
    __shared__ float red[32];

    const float2 e  = ((const float2*)(g_e    + (size_t)b * TT))[tid];
    const float2 hs = ((const float2*)(g_hsum + (size_t)b * TT))[tid];

    float m = fmaxf(e.x, e.y);
    #pragma unroll
    for (int off = 16; off; off >>= 1)
        m = fmaxf(m, __shfl_xor_sync(0xffffffffu, m, off));
    if (lane == 0) red[warp] = m;
    __syncthreads();
    float M = red[0];
    #pragma unroll
    for (int w = 1; w < 32; w++) M = fmaxf(M, red[w]);
    __syncthreads();

    const float ex0 = __expf(e.x - M);
    const float ex1 = __expf(e.y - M);
    float sum = ex0 + ex1;
    #pragma unroll
    for (int off = 16; off; off >>= 1)
        sum += __shfl_xor_sync(0xffffffffu, sum, off);
    if (lane == 0) red[warp] = sum;
    __syncthreads();
    float S = 0.f;
    #pragma unroll
    for (int w = 0; w < 32; w++) S += red[w];
    const float inv = 1.f / S;

    float2 o;
    o.x = ex0 * inv * hs.x;
    o.y = ex1 * inv * hs.y;
    ((float2*)(out + (size_t)b * TT))[tid] = o;
}

// ---------------------------------------------------------------------------
extern "C" void kernel_launch(void* const* d_in, const int* in_sizes, int n_in,
                              void* d_out, int out_size) {
    const float* s     = (const float*)d_in[0];   // [64, 512]
    const float* h     = (const float*)d_in[1];   // [64, 2048, 512]
    const float* phi_w = (const float*)d_in[2];   // [512, 512]
    const float* phi_b = (const float*)d_in[3];   // [512]
    const float* psi_w = (const float*)d_in[4];   // [512, 512]
    // d_in[5] = psi_b: unused (softmax shift invariance)
    float* out = (float*)d_out;                   // [64, 2048] fp32

    k_phis<<<dim3(32, 8), 256>>>(s, phi_w, phi_b);
    k_v<<<dim3(16, 4), 512>>>(psi_w);
    k_scores<<<8192, 256>>>(h);    // 8192 * 16 rows = 131072 = BB*TT
    k_softmax<<<64, 1024>>>(out);
}